// round 12
// baseline (speedup 1.0000x reference)
#include <cuda_runtime.h>
#include <cuda_bf16.h>

#define BQ 1024

// ---------- packed fp32x2 FMA (Blackwell FFMA2) ----------
union F2U { float2 f; unsigned long long u; };
__device__ __forceinline__ float2 ffma2(float2 a, float2 b, float2 c) {
    F2U A, B, C, D;
    A.f = a; B.f = b; C.f = c;
    asm("fma.rn.f32x2 %0, %1, %2, %3;" : "=l"(D.u) : "l"(A.u), "l"(B.u), "l"(C.u));
    return D.f;
}
__device__ __forceinline__ float2 mf2(float x, float y) { float2 r; r.x = x; r.y = y; return r; }

// ---------- cp.async helpers ----------
__device__ __forceinline__ unsigned su32(const void* p) {
    return (unsigned)__cvta_generic_to_shared(p);
}
#define CP16(dst_u32, src_ptr) \
    asm volatile("cp.async.cg.shared.global [%0], [%1], 16;\n" :: "r"(dst_u32), "l"(src_ptr))
#define CPCOMMIT() asm volatile("cp.async.commit_group;\n" ::: "memory")
#define CPWAIT0()  asm volatile("cp.async.wait_group 0;\n" ::: "memory")
#define CPWAIT1()  asm volatile("cp.async.wait_group 1;\n" ::: "memory")

// ---------- folded weights + scratch ----------
__device__ float g_s[64];
__device__ float g_AkT[512];    // [j][c]
__device__ float g_AqT[512];    // [j][c]
__device__ float g_ApT[64];     // [j][i]
__device__ float g_cb[8];
__device__ float g_Wv2[4096];   // [c][d] = Wv[d][c]
__device__ float g_hq[524288];  // [65536][8]  q@AqT

// 4 independent blocks: 0 -> s, 1 -> AkT+Wv2, 2 -> AqT, 3 -> ApT+cb
__global__ void precompute_kernel(
    const float* __restrict__ strength, const float* __restrict__ str_w,
    const float* __restrict__ str_b,
    const float* __restrict__ q_tbl, const float* __restrict__ k_tbl,
    const float* __restrict__ v_tbl,
    const float* __restrict__ attn_w1, const float* __restrict__ attn_b1,
    const float* __restrict__ pos_w2, const float* __restrict__ pos_b2,
    const int* __restrict__ embed_id)
{
    const int t = threadIdx.x;
    const int e = embed_id[0];
    const int bid = blockIdx.x;

    if (bid == 0) {
        __shared__ float red[256];
        const int o = t & 63, p = t >> 6;
        float acc = 0.f;
        for (int i = p * 128; i < (p + 1) * 128; ++i) acc += strength[i] * str_w[i * 64 + o];
        red[t] = acc;
        __syncthreads();
        if (t < 64) g_s[t] = red[t] + red[t + 64] + red[t + 128] + red[t + 192] + str_b[t];
    } else if (bid == 1) {
        for (int idx = t; idx < 512; idx += 256) {
            const int j = idx >> 6, c = idx & 63;
            float ak = 0.f;
            for (int dd = 0; dd < 64; ++dd)
                ak += k_tbl[e * 4096 + dd * 64 + c] * attn_w1[dd * 8 + j];
            g_AkT[idx] = ak;
        }
        for (int i = t; i < 4096; i += 256) {
            const int c = i >> 6, dd = i & 63;
            g_Wv2[c * 64 + dd] = v_tbl[e * 4096 + dd * 64 + c];
        }
    } else if (bid == 2) {
        for (int idx = t; idx < 512; idx += 256) {
            const int j = idx >> 6, c = idx & 63;
            float aq = 0.f;
            for (int dd = 0; dd < 64; ++dd)
                aq += q_tbl[e * 4096 + dd * 64 + c] * attn_w1[dd * 8 + j];
            g_AqT[idx] = aq;
        }
    } else {
        if (t < 64) {
            const int j = t >> 3, i = t & 7;
            float ap = 0.f;
            for (int dd = 0; dd < 64; ++dd) ap += pos_w2[i * 64 + dd] * attn_w1[dd * 8 + j];
            g_ApT[j * 8 + i] = ap;
        }
        if (t >= 64 && t < 72) {
            const int j = t - 64;
            float cb = attn_b1[j];
            for (int dd = 0; dd < 64; ++dd) cb += pos_b2[dd] * attn_w1[dd * 8 + j];
            g_cb[j] = cb;
        }
    }
}

// HQ = q @ AqT ; 64 q-rows per block.
__global__ __launch_bounds__(256, 2)
void hq_kernel(const float* __restrict__ q)
{
    __shared__ __align__(16) float s_q[64 * 68];
    __shared__ __align__(16) float s_aq[8 * 68];

    const int tid = threadIdx.x;
    const long row0 = (long)blockIdx.x * 64;

    const float4* qg = (const float4*)(q + row0 * 64);
    for (int i = tid; i < 1024; i += 256)
        CP16(su32(&s_q[(i >> 4) * 68 + (i & 15) * 4]), qg + i);
    CPCOMMIT();
    for (int i = tid; i < 512; i += 256)
        s_aq[(i >> 6) * 68 + (i & 63)] = g_AqT[i];
    CPWAIT0();
    __syncthreads();

    const int j = tid & 7, rr = tid >> 3;
    #pragma unroll
    for (int half = 0; half < 2; ++half) {
        const int row = rr + 32 * half;
        float2 a0 = mf2(0.f, 0.f), a1 = mf2(0.f, 0.f);
        const float4* qr = (const float4*)&s_q[row * 68];
        const float4* ar = (const float4*)&s_aq[j * 68];
        #pragma unroll
        for (int c4 = 0; c4 < 16; ++c4) {
            const float4 qq = qr[c4], aa = ar[c4];
            a0 = ffma2(mf2(qq.x, qq.y), mf2(aa.x, aa.y), a0);
            a1 = ffma2(mf2(qq.z, qq.w), mf2(aa.z, aa.w), a1);
        }
        g_hq[(row0 + row) * 8 + j] = (a0.x + a1.x) + (a0.y + a1.y);
    }
}

// ---------- fully fused kernel ----------
// dynamic smem layout (floats):
#define OFF_K     0        // 64*68 = 4352 (k rows for current pair of chunks)
#define OFF_W2    4352     // 4352  Wv [c][d] stride 68
#define OFF_VH    8704     // 4352  vh [row][d] stride 68 (64 rows)
#define OFF_AK    13056    // 544   AkT [j][c] stride 68
#define OFF_HKC   13600    // 512   hk [row][8] (64 rows)
#define OFF_S     14112    // 64
#define OFF_POS   14176    // 2*128
#define OFF_HQ    14432    // 2*32
#define OFF_PH    14496    // 256
#define OFF_HH    14752    // 256
#define OFF_XALL  15008    // 32*65 = 2080
#define OFF_APT   17088    // 64
#define OFF_PW1   17152    // 32
#define OFF_MASK  17184    // 2*32 ints
#define OFF_MBITS 17248    // 4 ints
#define SM_FLOATS 17252
#define SM_BYTES  (SM_FLOATS * 4)

__global__ __launch_bounds__(256, 3)
void attn_main(
    const float* __restrict__ k,
    const float* __restrict__ pos,
    const float* __restrict__ pos_w1, const float* __restrict__ pos_b1,
    const float* __restrict__ pos_w2, const float* __restrict__ pos_b2,
    const float* __restrict__ attn_w2, const float* __restrict__ attn_b2,
    const float* __restrict__ out_w, const float* __restrict__ out_b,
    const int* __restrict__ mask,
    float* __restrict__ out)
{
    extern __shared__ __align__(16) float sm[];
    float* s_k    = sm + OFF_K;
    float* s_w2   = sm + OFF_W2;
    float* s_vh   = sm + OFF_VH;
    float* s_ak   = sm + OFF_AK;
    float* s_hkc  = sm + OFF_HKC;
    float* s_s    = sm + OFF_S;
    float* s_posb = sm + OFF_POS;
    float* s_hqb  = sm + OFF_HQ;
    float* s_ph   = sm + OFF_PH;
    float* s_hh   = sm + OFF_HH;
    float* s_xall = sm + OFF_XALL;
    float* s_apT  = sm + OFF_APT;
    float* s_pw1  = sm + OFF_PW1;
    int*   s_maskb = (int*)(sm + OFF_MASK);
    int*   s_mbits = (int*)(sm + OFF_MBITS);

    const int tid = threadIdx.x;
    const int b = blockIdx.x;
    const int nbase = blockIdx.y * 32;
    const long nrow0 = (long)b * 64 + nbase;   // first n-row for this CTA

    // ---- prefetch chunk-0 small inputs (group 1), then k pair-0 (group 2) ----
    {
        if (tid < 32)       CP16(su32(&s_posb[tid * 4]), (const float4*)(pos + nrow0 * 32) + tid);
        else if (tid < 40)  { const int i = tid - 32; CP16(su32(&s_hqb[i * 4]), (const float4*)(g_hq + nrow0 * 8) + i); }
        else if (tid < 48)  { const int i = tid - 40; CP16(su32(&s_maskb[i * 4]), (const int4*)(mask + nrow0 * 8) + i); }
        CPCOMMIT();
        const float4* kg = (const float4*)(k + nrow0 * 512);   // 64 rows x 16 float4
        #pragma unroll
        for (int r = 0; r < 4; ++r) {
            const int i = tid + 256 * r;
            CP16(su32(&s_k[(i >> 4) * 68 + (i & 15) * 4]), kg + i);
        }
        CPCOMMIT();
    }

    // ---- one-time staging ----
    for (int i = tid; i < 4096; i += 256)
        s_w2[(i >> 6) * 68 + (i & 63)] = g_Wv2[i];
    for (int i = tid; i < 512; i += 256)
        s_ak[(i >> 6) * 68 + (i & 63)] = g_AkT[i];
    if (tid < 64) s_s[tid] = g_s[tid];
    if (tid < 64) s_apT[tid] = g_ApT[tid];
    if (tid < 32) s_pw1[tid] = pos_w1[tid];

    const int d  = tid & 63;
    const int j  = tid & 7;
    const int vA = (tid >> 3) & 7;
    const int ln = tid >> 6;
    const int ln8v = ln * 8 + vA;

    // G-phase thread mapping (vh_kernel style)
    const int lane = tid & 31, w = tid >> 5;
    const int dgG = lane & 7, rgG = lane >> 3;
    const int dbaseG = (w >> 2) * 32 + dgG * 4;
    const int rquartG = (w & 3) * 16;
    const int rrH = tid >> 3;    // HK row base (j = tid&7)

    float2 aw2r[4], pw2r[4];
    #pragma unroll
    for (int p = 0; p < 4; ++p) {
        aw2r[p] = mf2(attn_w2[(2 * p) * 64 + d], attn_w2[(2 * p + 1) * 64 + d]);
        pw2r[p] = mf2(pos_w2[(2 * p) * 64 + d], pos_w2[(2 * p + 1) * 64 + d]);
    }
    const float ab2d = attn_b2[d];
    const float pb2d = pos_b2[d];
    const float cbj  = g_cb[j];
    const float pb1j = pos_b1[j];

    for (int chunk = 0; chunk < 8; ++chunk) {
        const int pb = chunk & 1;
        const long base_n = nrow0 + chunk * 4;
        float* s_pos = s_posb + pb * 128;
        float* s_hq  = s_hqb + pb * 32;
        int*   s_msk = s_maskb + pb * 32;
        const int po = chunk & 1;                  // row offset selector in s_vh/s_hkc

        if ((chunk & 1) == 0) {
            CPWAIT0();              // k(pair) + pos(chunk) ready
            __syncthreads();

            // ---- G phase: vh + hk for 64 rows ----
            {
                float2 acc[4][2];
                #pragma unroll
                for (int r = 0; r < 4; ++r) { acc[r][0] = mf2(0.f, 0.f); acc[r][1] = mf2(0.f, 0.f); }
                #pragma unroll
                for (int c4 = 0; c4 < 16; ++c4) {
                    float4 k4[4];
                    #pragma unroll
                    for (int r = 0; r < 4; ++r)
                        k4[r] = *(const float4*)&s_k[(rquartG + rgG + 4 * r) * 68 + c4 * 4];
                    #pragma unroll
                    for (int cs = 0; cs < 4; ++cs) {
                        const float4 w4 = *(const float4*)&s_w2[(c4 * 4 + cs) * 68 + dbaseG];
                        const float2 wlo = mf2(w4.x, w4.y), whi = mf2(w4.z, w4.w);
                        #pragma unroll
                        for (int r = 0; r < 4; ++r) {
                            const float kv = (cs == 0) ? k4[r].x : (cs == 1) ? k4[r].y
                                           : (cs == 2) ? k4[r].z : k4[r].w;
                            acc[r][0] = ffma2(mf2(kv, kv), wlo, acc[r][0]);
                            acc[r][1] = ffma2(mf2(kv, kv), whi, acc[r][1]);
                        }
                    }
                }
                const float4 s4 = *(const float4*)&s_s[dbaseG];
                #pragma unroll
                for (int r = 0; r < 4; ++r) {
                    float4 o;
                    o.x = acc[r][0].x + s4.x; o.y = acc[r][0].y + s4.y;
                    o.z = acc[r][1].x + s4.z; o.w = acc[r][1].y + s4.w;
                    *(float4*)&s_vh[(rquartG + rgG + 4 * r) * 68 + dbaseG] = o;
                }
                // HK: 2 rows per thread
                #pragma unroll
                for (int half = 0; half < 2; ++half) {
                    const int row = rrH + 32 * half;
                    float2 a0 = mf2(0.f, 0.f), a1 = mf2(0.f, 0.f);
                    const float4* kr = (const float4*)&s_k[row * 68];
                    const float4* ar = (const float4*)&s_ak[j * 68];
                    #pragma unroll
                    for (int c4 = 0; c4 < 16; ++c4) {
                        const float4 kk = kr[c4], aa = ar[c4];
                        a0 = ffma2(mf2(kk.x, kk.y), mf2(aa.x, aa.y), a0);
                        a1 = ffma2(mf2(kk.z, kk.w), mf2(aa.z, aa.w), a1);
                    }
                    s_hkc[row * 8 + j] = (a0.x + a1.x) + (a0.y + a1.y);
                }
            }
            __syncthreads();   // s_vh/s_hkc visible; s_k reads complete

            // prefetch next chunk's small inputs (group), THEN next pair's k (group)
            if (chunk < 7) {
                const long bn1 = base_n + 4;
                if (tid < 32)       CP16(su32(&s_posb[(1 - pb) * 128 + tid * 4]), (const float4*)(pos + bn1 * 32) + tid);
                else if (tid < 40)  { const int i = tid - 32; CP16(su32(&s_hqb[(1 - pb) * 32 + i * 4]), (const float4*)(g_hq + bn1 * 8) + i); }
                else if (tid < 48)  { const int i = tid - 40; CP16(su32(&s_maskb[(1 - pb) * 32 + i * 4]), (const int4*)(mask + bn1 * 8) + i); }
                CPCOMMIT();
            }
            if (chunk < 6) {
                const float4* kg = (const float4*)(k + (base_n + 8) * 512);
                #pragma unroll
                for (int r = 0; r < 4; ++r) {
                    const int i = tid + 256 * r;
                    CP16(su32(&s_k[(i >> 4) * 68 + (i & 15) * 4]), kg + i);
                }
                CPCOMMIT();
            }
        } else {
            if (chunk == 7) { CPWAIT0(); } else { CPWAIT1(); }   // pos ready; k may pend
            __syncthreads();
            if (chunk < 7) {
                const long bn1 = base_n + 4;
                if (tid < 32)       CP16(su32(&s_posb[(1 - pb) * 128 + tid * 4]), (const float4*)(pos + bn1 * 32) + tid);
                else if (tid < 40)  { const int i = tid - 32; CP16(su32(&s_hqb[(1 - pb) * 32 + i * 4]), (const float4*)(g_hq + bn1 * 8) + i); }
                else if (tid < 48)  { const int i = tid - 40; CP16(su32(&s_maskb[(1 - pb) * 32 + i * 4]), (const int4*)(mask + bn1 * 8) + i); }
                CPCOMMIT();
            }
        }

        // ---- phase A1: pos-MLP hidden + mask pack ----
        {
            const float4 p4 = *reinterpret_cast<const float4*>(&s_pos[ln8v * 4]);
            float acc = pb1j;
            acc += p4.x * s_pw1[0 * 8 + j];
            acc += p4.y * s_pw1[1 * 8 + j];
            acc += p4.z * s_pw1[2 * 8 + j];
            acc += p4.w * s_pw1[3 * 8 + j];
            s_ph[ln8v * 8 + j] = fmaxf(acc, 0.f);
        }
        if (tid < 4) {
            const int4 m0 = *reinterpret_cast<const int4*>(&s_msk[tid * 8]);
            const int4 m1 = *reinterpret_cast<const int4*>(&s_msk[tid * 8 + 4]);
            int bits = 0;
            bits |= (m0.x != 0) << 0; bits |= (m0.y != 0) << 1;
            bits |= (m0.z != 0) << 2; bits |= (m0.w != 0) << 3;
            bits |= (m1.x != 0) << 4; bits |= (m1.y != 0) << 5;
            bits |= (m1.z != 0) << 6; bits |= (m1.w != 0) << 7;
            s_mbits[tid] = bits;
        }
        __syncthreads();

        // ---- phase A2: attn hidden = relu(hk - hq + ph@Ap + cb) ----
        {
            float2 acc0 = mf2(s_hkc[(po * 32 + ln8v) * 8 + j] - s_hq[ln * 8 + j] + cbj, 0.f);
            float2 acc1 = mf2(0.f, 0.f);
            const float4* phr = reinterpret_cast<const float4*>(s_ph + ln8v * 8);
            const float4  h0 = phr[0], h1 = phr[1];
            const float4* apr = reinterpret_cast<const float4*>(s_apT + j * 8);
            const float4  a0 = apr[0], a1 = apr[1];
            acc0 = ffma2(mf2(h0.x, h0.y), mf2(a0.x, a0.y), acc0);
            acc1 = ffma2(mf2(h0.z, h0.w), mf2(a0.z, a0.w), acc1);
            acc0 = ffma2(mf2(h1.x, h1.y), mf2(a1.x, a1.y), acc0);
            acc1 = ffma2(mf2(h1.z, h1.w), mf2(a1.z, a1.w), acc1);
            s_hh[ln8v * 8 + j] = fmaxf((acc0.x + acc1.x) + (acc0.y + acc1.y), 0.f);
        }
        __syncthreads();

        // ---- phase B: logits + val, softmax over V ----
        {
            const int mbits = s_mbits[ln];
            float logit[8], val[8];
            #pragma unroll
            for (int v = 0; v < 8; ++v) {
                const int rv = ln * 8 + v;
                const float4* hhr = reinterpret_cast<const float4*>(s_hh + rv * 8);
                const float4 h0 = hhr[0], h1 = hhr[1];
                float2 a2 = ffma2(mf2(h0.x, h0.y), aw2r[0], mf2(ab2d, 0.f));
                float2 a3 = ffma2(mf2(h0.z, h0.w), aw2r[1], mf2(0.f, 0.f));
                a2 = ffma2(mf2(h1.x, h1.y), aw2r[2], a2);
                a3 = ffma2(mf2(h1.z, h1.w), aw2r[3], a3);

                const float4* phr = reinterpret_cast<const float4*>(s_ph + rv * 8);
                const float4 p0 = phr[0], p1 = phr[1];
                float2 pv = ffma2(mf2(p0.x, p0.y), pw2r[0], mf2(pb2d, 0.f));
                float2 pw = ffma2(mf2(p0.z, p0.w), pw2r[1], mf2(0.f, 0.f));
                pv = ffma2(mf2(p1.x, p1.y), pw2r[2], pv);
                pw = ffma2(mf2(p1.z, p1.w), pw2r[3], pw);

                logit[v] = ((mbits >> v) & 1) ? ((a2.x + a3.x) + (a2.y + a3.y)) : -1e9f;
                val[v] = s_vh[(po * 32 + rv) * 68 + d] + (pv.x + pw.x) + (pv.y + pw.y);
            }
            const float m01 = fmaxf(fmaxf(logit[0], logit[1]), fmaxf(logit[2], logit[3]));
            const float m23 = fmaxf(fmaxf(logit[4], logit[5]), fmaxf(logit[6], logit[7]));
            const float m = fmaxf(m01, m23);
            float ev[8];
            #pragma unroll
            for (int v = 0; v < 8; ++v) ev[v] = __expf(logit[v] - m);
            const float ssum = ((ev[0] + ev[1]) + (ev[2] + ev[3]))
                             + ((ev[4] + ev[5]) + (ev[6] + ev[7]));
            const float wacc = ((ev[0] * val[0] + ev[1] * val[1]) + (ev[2] * val[2] + ev[3] * val[3]))
                             + ((ev[4] * val[4] + ev[5] * val[5]) + (ev[6] * val[6] + ev[7] * val[7]));
            s_xall[(chunk * 4 + ln) * 65 + d] = __fdividef(wacc, ssum);
        }
        // next iteration's wait+sync closes this chunk
    }
    __syncthreads();

    // ---- deferred output GEMM: 32 rows x 64 d; out_w via __ldg ----
    {
        const int dblk = (tid & 15) * 4;
        const int rp = tid >> 4;                 // 0..15
        const float4 ob4 = *reinterpret_cast<const float4*>(out_b + dblk);
        float2 a0 = mf2(ob4.x, ob4.y), a1 = mf2(ob4.z, ob4.w);
        float2 b0 = a0, b1 = a1;
        const float* x0p = s_xall + rp * 65;
        const float* x1p = s_xall + (rp + 16) * 65;
        #pragma unroll
        for (int c = 0; c < 64; ++c) {
            const float4 w4 = __ldg(reinterpret_cast<const float4*>(out_w + c * 64 + dblk));
            const float2 wlo = mf2(w4.x, w4.y), whi = mf2(w4.z, w4.w);
            const float xv0 = x0p[c], xv1 = x1p[c];
            a0 = ffma2(mf2(xv0, xv0), wlo, a0);
            a1 = ffma2(mf2(xv0, xv0), whi, a1);
            b0 = ffma2(mf2(xv1, xv1), wlo, b0);
            b1 = ffma2(mf2(xv1, xv1), whi, b1);
        }
        float4 o;
        o.x = a0.x; o.y = a0.y; o.z = a1.x; o.w = a1.y;
        *reinterpret_cast<float4*>(out + (nrow0 + rp) * 64 + dblk) = o;
        o.x = b0.x; o.y = b0.y; o.z = b1.x; o.w = b1.y;
        *reinterpret_cast<float4*>(out + (nrow0 + rp + 16) * 64 + dblk) = o;
    }
}

extern "C" void kernel_launch(void* const* d_in, const int* in_sizes, int n_in,
                              void* d_out, int out_size)
{
    const float* q        = (const float*)d_in[0];
    const float* k        = (const float*)d_in[1];
    const float* pos      = (const float*)d_in[2];
    const float* strength = (const float*)d_in[3];
    const float* q_tbl    = (const float*)d_in[4];
    const float* k_tbl    = (const float*)d_in[5];
    const float* v_tbl    = (const float*)d_in[6];
    const float* pos_w1   = (const float*)d_in[7];
    const float* pos_b1   = (const float*)d_in[8];
    const float* pos_w2   = (const float*)d_in[9];
    const float* pos_b2   = (const float*)d_in[10];
    const float* attn_w1  = (const float*)d_in[11];
    const float* attn_b1  = (const float*)d_in[12];
    const float* attn_w2  = (const float*)d_in[13];
    const float* attn_b2  = (const float*)d_in[14];
    const float* out_w    = (const float*)d_in[15];
    const float* out_b    = (const float*)d_in[16];
    const float* str_w    = (const float*)d_in[17];
    const float* str_b    = (const float*)d_in[18];
    const int*   mask     = (const int*)d_in[19];
    const int*   embed_id = (const int*)d_in[20];
    float* out = (float*)d_out;

    static bool attr_set = false;
    if (!attr_set) {
        cudaFuncSetAttribute(attn_main, cudaFuncAttributeMaxDynamicSharedMemorySize, SM_BYTES);
        attr_set = true;
    }

    precompute_kernel<<<4, 256>>>(strength, str_w, str_b, q_tbl, k_tbl, v_tbl,
                                  attn_w1, attn_b1, pos_w2, pos_b2, embed_id);

    hq_kernel<<<1024, 256>>>(q);

    dim3 grid(BQ, 2);
    attn_main<<<grid, 256, SM_BYTES>>>(k, pos,
                                       pos_w1, pos_b1, pos_w2, pos_b2,
                                       attn_w2, attn_b2, out_w, out_b,
                                       mask, out);
}